// round 3
// baseline (speedup 1.0000x reference)
#include <cuda_runtime.h>
#include <cuda_bf16.h>
#include <cstdint>
#include <cstddef>

#define Bn   32
#define Vn   256
#define En   4
#define Mn   16
#define U1n  128
#define F1n  144      // M + U1
#define U2n  64
#define F2n  80       // U2 + M
#define AUXn 128
#define L1n  256
#define L2n  256
#define EMBn 266240   // E*V*V + V*M
#define BEMB ((size_t)Bn*EMBn)

// ---------------- scratch (static device memory; no allocs) ----------------
__device__ float g_ann1 [Bn*Vn*F1n];      // [b][v][ node(16) | h0(128) ]
__device__ float g_P1   [Bn*En*Vn*U2n];   // per-edge projected features
__device__ float g_ann2 [Bn*Vn*F2n];      // [b][v][ h1(64) | node(16) ]
__device__ float g_poolp[4*Bn*AUXn];      // pooling partial sums (4 v-chunks)
__device__ float g_o2   [Bn*L2n];         // dense head output

__device__ __forceinline__ float sigmoidf_(float x){ return 1.0f/(1.0f+expf(-x)); }

__device__ __forceinline__ unsigned long long fma2_(unsigned long long a,
                                                    unsigned long long b,
                                                    unsigned long long c){
  unsigned long long d;
  asm("fma.rn.f32x2 %0, %1, %2, %3;" : "=l"(d) : "l"(a), "l"(b), "l"(c));
  return d;
}

// ---------------- K1: GCL layer 0 (reformulated) ---------------------------
// out[v,u] = (adj^T [node|1])[v,(e,f)] @ [W0;b0][(e,f),u] + node@W2_0 + b2_0
// grid (8, B), block 256
__global__ void k1_gcl0(const float* __restrict__ adj, const float* __restrict__ node,
                        const float* __restrict__ W0,  const float* __restrict__ b0,
                        const float* __restrict__ W2,  const float* __restrict__ b2){
  extern __shared__ float sm[];
  float* sNode = sm;                 // 256*17  (node + ones column)
  float* sW    = sNode + Vn*17;      // 68*128
  float* sW2   = sW    + 68*U1n;     // 16*128
  float* sB2   = sW2   + Mn*U1n;     // 128
  float* sAdj  = sB2   + U1n;        // 32*257 (padded)
  float* sA2   = sAdj  + 32*257;     // 32*68
  const int tid = threadIdx.x;
  const int b = blockIdx.y, v0 = blockIdx.x*32;

  for (int idx = tid; idx < Vn*17; idx += 256){
    int v = idx/17, f = idx - v*17;
    sNode[idx] = (f < Mn) ? node[((size_t)b*Vn+v)*Mn + f] : 1.0f;
  }
  for (int idx = tid; idx < 68*U1n; idx += 256){
    int k = idx >> 7, u = idx & 127;
    int e = k/17, f = k - e*17;
    sW[idx] = (f < Mn) ? W0[((size_t)e*Mn+f)*U1n + u] : b0[e*U1n + u];
  }
  for (int idx = tid; idx < Mn*U1n; idx += 256) sW2[idx] = W2[idx];
  for (int idx = tid; idx < U1n;    idx += 256) sB2[idx] = b2[idx];
  __syncthreads();

  for (int e = 0; e < En; ++e){
    for (int idx = tid; idx < 32*Vn; idx += 256){
      int vl = idx >> 8, w = idx & 255;
      sAdj[vl*257 + w] = adj[(((size_t)b*(En+1) + e)*Vn + (v0+vl))*(size_t)Vn + w];
    }
    __syncthreads();
    for (int idx = tid; idx < 32*17; idx += 256){
      int vl = idx/17, f = idx - vl*17;
      const float* arow = sAdj + vl*257;
      float acc = 0.f;
      #pragma unroll 8
      for (int w = 0; w < Vn; ++w) acc += arow[w]*sNode[w*17+f];
      sA2[vl*68 + e*17 + f] = acc;
    }
    __syncthreads();
  }

  const int ug = tid & 7, vl = tid >> 3;
  float acc[16];
  #pragma unroll
  for (int i = 0; i < 16; ++i) acc[i] = sB2[ug + 8*i];
  const float* a2 = sA2 + vl*68;
  for (int k = 0; k < 68; ++k){
    float a = a2[k];
    const float* wr = sW + k*U1n + ug;
    #pragma unroll
    for (int i = 0; i < 16; ++i) acc[i] += a*wr[8*i];
  }
  const float* nr = sNode + (v0+vl)*17;
  #pragma unroll
  for (int f = 0; f < Mn; ++f){
    float a = nr[f];
    const float* wr = sW2 + f*U1n + ug;
    #pragma unroll
    for (int i = 0; i < 16; ++i) acc[i] += a*wr[8*i];
  }
  float* dst = g_ann1 + ((size_t)b*Vn + v0+vl)*F1n + Mn;
  #pragma unroll
  for (int i = 0; i < 16; ++i) dst[ug + 8*i] = tanhf(acc[i]);
  for (int idx = tid; idx < 32*Mn; idx += 256){
    int v = idx >> 4, f = idx & 15;
    g_ann1[((size_t)b*Vn + v0+v)*F1n + f] = sNode[(v0+v)*17 + f];
  }
}

// ---------------- K2: P1[b,e,w,:] = ann1[b,w,:] @ W_adj1[e] + b_adj1[e] ----
// grid (E, B), block 256
__global__ void k2_p1(const float* __restrict__ W1, const float* __restrict__ b1){
  extern __shared__ float sm[];
  float* sW1  = sm;                 // 144*64
  float* sB1  = sW1 + F1n*U2n;      // 64
  float* sAnn = sB1 + U2n;          // 64*145 (padded)
  const int tid = threadIdx.x;
  const int e = blockIdx.x, b = blockIdx.y;
  for (int idx = tid; idx < F1n*U2n; idx += 256) sW1[idx] = W1[(size_t)e*F1n*U2n + idx];
  for (int idx = tid; idx < U2n;     idx += 256) sB1[idx] = b1[e*U2n + idx];
  __syncthreads();
  const int ug = tid & 3, wl = tid >> 2;
  for (int wc = 0; wc < 4; ++wc){
    for (int idx = tid; idx < 64*F1n; idx += 256){
      int w = idx/F1n, f = idx - w*F1n;
      sAnn[w*145 + f] = g_ann1[((size_t)b*Vn + wc*64 + w)*F1n + f];
    }
    __syncthreads();
    float acc[16];
    #pragma unroll
    for (int i = 0; i < 16; ++i) acc[i] = sB1[ug + 4*i];
    const float* ar = sAnn + wl*145;
    for (int f = 0; f < F1n; ++f){
      float a = ar[f];
      const float* wr = sW1 + f*U2n + ug;
      #pragma unroll
      for (int i = 0; i < 16; ++i) acc[i] += a*wr[4*i];
    }
    float* dst = g_P1 + (((size_t)b*En + e)*Vn + wc*64 + wl)*U2n;
    #pragma unroll
    for (int i = 0; i < 16; ++i) dst[ug + 4*i] = acc[i];
    __syncthreads();
  }
}

// ---------------- K3: GCL layer 1 contraction + W2 term + concat -> ann2 ---
// grid (8, B), block 256
__global__ void k3_gcl1(const float* __restrict__ adj, const float* __restrict__ node,
                        const float* __restrict__ W2,  const float* __restrict__ b2){
  extern __shared__ float sm[];
  float* sAdj = sm;               // 32*257 (padded)
  float* sP   = sAdj + 32*257;    // 64*64
  float* sW2  = sP   + 64*64;     // 144*64
  float* sB2  = sW2  + F1n*U2n;   // 64
  float* sAnn = sB2  + U2n;       // 32*145 (padded)
  const int tid = threadIdx.x;
  const int b = blockIdx.y, v0 = blockIdx.x*32;
  for (int idx = tid; idx < F1n*U2n; idx += 256) sW2[idx] = W2[idx];
  for (int idx = tid; idx < U2n;     idx += 256) sB2[idx] = b2[idx];
  for (int idx = tid; idx < 32*F1n;  idx += 256){
    int vl = idx/F1n, f = idx - vl*F1n;
    sAnn[vl*145+f] = g_ann1[((size_t)b*Vn + v0+vl)*F1n + f];
  }
  __syncthreads();
  const int ug = tid & 7, vl = tid >> 3;
  float acc[8];
  #pragma unroll
  for (int i = 0; i < 8; ++i) acc[i] = sB2[ug+8*i];
  const float* ar = sAnn + vl*145;
  for (int f = 0; f < F1n; ++f){
    float a = ar[f];
    const float* wr = sW2 + f*U2n + ug;
    #pragma unroll
    for (int i = 0; i < 8; ++i) acc[i] += a*wr[8*i];
  }
  for (int e = 0; e < En; ++e){
    for (int idx = tid; idx < 32*Vn; idx += 256){
      int v = idx >> 8, w = idx & 255;
      sAdj[v*257+w] = adj[(((size_t)b*(En+1)+e)*Vn + v0+v)*(size_t)Vn + w];
    }
    __syncthreads();
    for (int wc = 0; wc < 4; ++wc){
      for (int idx = tid; idx < 64*U2n; idx += 256)
        sP[idx] = g_P1[(((size_t)b*En + e)*Vn + wc*64)*U2n + idx];
      __syncthreads();
      const float* arow = sAdj + vl*257 + wc*64;
      #pragma unroll 4
      for (int w = 0; w < 64; ++w){
        float a = arow[w];
        const float* pr = sP + w*U2n + ug;
        #pragma unroll
        for (int i = 0; i < 8; ++i) acc[i] += a*pr[8*i];
      }
      __syncthreads();
    }
  }
  float* dst = g_ann2 + ((size_t)b*Vn + v0+vl)*F2n;
  #pragma unroll
  for (int i = 0; i < 8; ++i) dst[ug+8*i] = tanhf(acc[i]);
  for (int idx = tid; idx < 32*Mn; idx += 256){
    int v = idx >> 4, f = idx & 15;
    g_ann2[((size_t)b*Vn + v0+v)*F2n + U2n + f] = node[((size_t)b*Vn + v0+v)*Mn + f];
  }
}

// ---------------- K4: gated pooling, deterministic partial sums ------------
// grid (4, B), block 256
__global__ void k4_pool(const float* __restrict__ Wi, const float* __restrict__ bi,
                        const float* __restrict__ Wj, const float* __restrict__ bj){
  extern __shared__ float sm[];
  float* sWi  = sm;                 // 80*128
  float* sWj  = sWi + F2n*AUXn;     // 80*128
  float* sbi  = sWj + F2n*AUXn;     // 128
  float* sbj  = sbi + AUXn;         // 128
  float* sAnn = sbj + AUXn;         // 64*80
  float* sRed = sAnn + 64*F2n;      // 8*128
  const int tid = threadIdx.x;
  const int vc = blockIdx.x, b = blockIdx.y;
  for (int idx = tid; idx < F2n*AUXn; idx += 256){ sWi[idx] = Wi[idx]; sWj[idx] = Wj[idx]; }
  for (int idx = tid; idx < AUXn;     idx += 256){ sbi[idx] = bi[idx]; sbj[idx] = bj[idx]; }
  for (int idx = tid; idx < 64*F2n;   idx += 256)
    sAnn[idx] = g_ann2[((size_t)b*Vn + vc*64)*F2n + idx];
  __syncthreads();
  const int ul = tid & 31, vg = tid >> 5;   // warp-uniform vg -> smem broadcast
  float si[8][4], sj[8][4];
  #pragma unroll
  for (int j = 0; j < 8; ++j)
    #pragma unroll
    for (int i = 0; i < 4; ++i){ si[j][i] = sbi[ul+32*i]; sj[j][i] = sbj[ul+32*i]; }
  for (int f = 0; f < F2n; ++f){
    float wi[4], wj[4];
    #pragma unroll
    for (int i = 0; i < 4; ++i){ wi[i] = sWi[f*AUXn + ul+32*i]; wj[i] = sWj[f*AUXn + ul+32*i]; }
    #pragma unroll
    for (int j = 0; j < 8; ++j){
      float a = sAnn[(vg*8+j)*F2n + f];
      #pragma unroll
      for (int i = 0; i < 4; ++i){ si[j][i] += a*wi[i]; sj[j][i] += a*wj[i]; }
    }
  }
  float pool[4] = {0.f,0.f,0.f,0.f};
  #pragma unroll
  for (int j = 0; j < 8; ++j)
    #pragma unroll
    for (int i = 0; i < 4; ++i)
      pool[i] += sigmoidf_(si[j][i]) * tanhf(sj[j][i]);
  #pragma unroll
  for (int i = 0; i < 4; ++i) sRed[vg*AUXn + ul + 32*i] = pool[i];
  __syncthreads();
  if (tid < AUXn){
    float s = 0.f;
    #pragma unroll
    for (int g = 0; g < 8; ++g) s += sRed[g*AUXn + tid];
    g_poolp[((size_t)vc*Bn + b)*AUXn + tid] = s;
  }
}

// ---------------- K5: dense head (o -> tanh -> d1 -> d2) -------------------
// grid B, block 256
__global__ void k5_dense(const float* __restrict__ Wd1, const float* __restrict__ bd1,
                         const float* __restrict__ Wd2, const float* __restrict__ bd2){
  __shared__ float so [AUXn];
  __shared__ float so1[L1n];
  const int tid = threadIdx.x, b = blockIdx.x;
  if (tid < AUXn){
    float s = 0.f;
    #pragma unroll
    for (int vc = 0; vc < 4; ++vc) s += g_poolp[((size_t)vc*Bn + b)*AUXn + tid];
    so[tid] = tanhf(s);
  }
  __syncthreads();
  float acc = bd1[tid];
  #pragma unroll 4
  for (int k = 0; k < AUXn; ++k) acc += so[k]*Wd1[k*L1n + tid];
  so1[tid] = tanhf(acc);
  __syncthreads();
  acc = bd2[tid];
  #pragma unroll 4
  for (int k = 0; k < L1n; ++k) acc += so1[k]*Wd2[k*L2n + tid];
  g_o2[b*L2n + tid] = tanhf(acc);
}

// ---------------- K6: mu / logvar GEMMs + reparameterization ---------------
// grid EMB/256 = 1040, block 256, smem 64KB (o2 duplicated as f32x2).
// Each thread: 4 contiguous n (1 LDG.128/STG.128) x 8 b.
__global__ void __launch_bounds__(256, 2)
k6_head(const float* __restrict__ Wmu, const float* __restrict__ bmu,
        const float* __restrict__ Wlv, const float* __restrict__ blv,
        const float* __restrict__ eps, float* __restrict__ out){
  extern __shared__ float sm[];
  float2* sOd = (float2*)sm;          // [k][b] o2 duplicated -> fma2 a-operand
  const int tid = threadIdx.x;
  const int n0 = blockIdx.x * 256;
  const int ng = tid & 63, bg = tid >> 6;   // warp-uniform bg -> smem broadcast

  for (int idx = tid; idx < L2n*Bn; idx += 256){
    int k = idx >> 5, b = idx & 31;
    float v = g_o2[b*L2n + k];
    sOd[idx] = make_float2(v, v);
  }
  __syncthreads();

  unsigned long long acc[8][2];
  unsigned long long mu [8][2];

  // ---- pass 1: mu ----
  {
    float4 b4 = ((const float4*)(bmu + n0))[ng];
    unsigned long long bi0 = ((unsigned long long*)&b4)[0];
    unsigned long long bi1 = ((unsigned long long*)&b4)[1];
    #pragma unroll
    for (int j = 0; j < 8; ++j){ acc[j][0] = bi0; acc[j][1] = bi1; }
    #pragma unroll 4
    for (int k = 0; k < L2n; ++k){
      float4 w4 = ((const float4*)(Wmu + (size_t)k*EMBn + n0))[ng];
      unsigned long long w0 = ((unsigned long long*)&w4)[0];
      unsigned long long w1 = ((unsigned long long*)&w4)[1];
      const unsigned long long* od = (const unsigned long long*)(sOd + k*Bn + bg*8);
      #pragma unroll
      for (int j = 0; j < 8; ++j){
        unsigned long long o = od[j];
        acc[j][0] = fma2_(o, w0, acc[j][0]);
        acc[j][1] = fma2_(o, w1, acc[j][1]);
      }
    }
    #pragma unroll
    for (int j = 0; j < 8; ++j){
      int b = bg*8 + j;
      float4 r;
      ((unsigned long long*)&r)[0] = acc[j][0];
      ((unsigned long long*)&r)[1] = acc[j][1];
      ((float4*)(out + BEMB + (size_t)b*EMBn + n0))[ng] = r;
      mu[j][0] = acc[j][0]; mu[j][1] = acc[j][1];
    }
  }

  // ---- pass 2: logvar + reparameterize ----
  {
    float4 b4 = ((const float4*)(blv + n0))[ng];
    unsigned long long bi0 = ((unsigned long long*)&b4)[0];
    unsigned long long bi1 = ((unsigned long long*)&b4)[1];
    #pragma unroll
    for (int j = 0; j < 8; ++j){ acc[j][0] = bi0; acc[j][1] = bi1; }
    #pragma unroll 4
    for (int k = 0; k < L2n; ++k){
      float4 w4 = ((const float4*)(Wlv + (size_t)k*EMBn + n0))[ng];
      unsigned long long w0 = ((unsigned long long*)&w4)[0];
      unsigned long long w1 = ((unsigned long long*)&w4)[1];
      const unsigned long long* od = (const unsigned long long*)(sOd + k*Bn + bg*8);
      #pragma unroll
      for (int j = 0; j < 8; ++j){
        unsigned long long o = od[j];
        acc[j][0] = fma2_(o, w0, acc[j][0]);
        acc[j][1] = fma2_(o, w1, acc[j][1]);
      }
    }
    #pragma unroll
    for (int j = 0; j < 8; ++j){
      int b = bg*8 + j;
      float4 lv;
      ((unsigned long long*)&lv)[0] = acc[j][0];
      ((unsigned long long*)&lv)[1] = acc[j][1];
      ((float4*)(out + 2*BEMB + (size_t)b*EMBn + n0))[ng] = lv;
      float4 e4 = ((const float4*)(eps + (size_t)b*EMBn + n0))[ng];
      float4 m4;
      ((unsigned long long*)&m4)[0] = mu[j][0];
      ((unsigned long long*)&m4)[1] = mu[j][1];
      float4 h;
      h.x = fmaf(e4.x, expf(0.5f*lv.x), m4.x);
      h.y = fmaf(e4.y, expf(0.5f*lv.y), m4.y);
      h.z = fmaf(e4.z, expf(0.5f*lv.z), m4.z);
      h.w = fmaf(e4.w, expf(0.5f*lv.w), m4.w);
      ((float4*)(out + (size_t)b*EMBn + n0))[ng] = h;
    }
  }
}

// ---------------------------------------------------------------------------
extern "C" void kernel_launch(void* const* d_in, const int* in_sizes, int n_in,
                              void* d_out, int out_size) {
  const float* adj  = (const float*)d_in[0];
  const float* node = (const float*)d_in[1];
  const float* W0   = (const float*)d_in[2];
  const float* b0   = (const float*)d_in[3];
  const float* W2_0 = (const float*)d_in[4];
  const float* b2_0 = (const float*)d_in[5];
  const float* W1   = (const float*)d_in[6];
  const float* b1   = (const float*)d_in[7];
  const float* W2_1 = (const float*)d_in[8];
  const float* b2_1 = (const float*)d_in[9];
  const float* Wi   = (const float*)d_in[10];
  const float* bi   = (const float*)d_in[11];
  const float* Wj   = (const float*)d_in[12];
  const float* bj   = (const float*)d_in[13];
  const float* Wd1  = (const float*)d_in[14];
  const float* bd1  = (const float*)d_in[15];
  const float* Wd2  = (const float*)d_in[16];
  const float* bd2  = (const float*)d_in[17];
  const float* Wmu  = (const float*)d_in[18];
  const float* bmu  = (const float*)d_in[19];
  const float* Wlv  = (const float*)d_in[20];
  const float* blv  = (const float*)d_in[21];
  const float* eps  = (const float*)d_in[22];
  float* out = (float*)d_out;

  const int smem1 = (Vn*17 + 68*U1n + Mn*U1n + U1n + 32*257 + 32*68) * 4;
  const int smem2 = (F1n*U2n + U2n + 64*145) * 4;
  const int smem3 = (32*257 + 64*64 + F1n*U2n + U2n + 32*145) * 4;
  const int smem4 = (2*F2n*AUXn + 2*AUXn + 64*F2n + 8*AUXn) * 4;
  const int smem6 = L2n*Bn*8;

  cudaFuncSetAttribute(k1_gcl0, cudaFuncAttributeMaxDynamicSharedMemorySize, smem1);
  cudaFuncSetAttribute(k2_p1,   cudaFuncAttributeMaxDynamicSharedMemorySize, smem2);
  cudaFuncSetAttribute(k3_gcl1, cudaFuncAttributeMaxDynamicSharedMemorySize, smem3);
  cudaFuncSetAttribute(k4_pool, cudaFuncAttributeMaxDynamicSharedMemorySize, smem4);
  cudaFuncSetAttribute(k6_head, cudaFuncAttributeMaxDynamicSharedMemorySize, smem6);

  k1_gcl0<<<dim3(8, Bn), 256, smem1>>>(adj, node, W0, b0, W2_0, b2_0);
  k2_p1  <<<dim3(En, Bn), 256, smem2>>>(W1, b1);
  k3_gcl1<<<dim3(8, Bn), 256, smem3>>>(adj, node, W2_1, b2_1);
  k4_pool<<<dim3(4, Bn), 256, smem4>>>(Wi, bi, Wj, bj);
  k5_dense<<<Bn, 256>>>(Wd1, bd1, Wd2, bd2);
  k6_head<<<EMBn/256, 256, smem6>>>(Wmu, bmu, Wlv, blv, eps, out);
}